// round 1
// baseline (speedup 1.0000x reference)
#include <cuda_runtime.h>

#define BB 64
#define CC 768
#define SS 8
#define HH 28
#define WW 28
#define HW 784
#define LEARNED_SIZE (BB*CC*SS)   /* 393216 */
#define MASK_SIZE    (BB*SS*HW)   /* 401408 */

#define CGRP 16                   /* channel groups per batch for conv */
#define CH_PER (CC/CGRP)          /* 48 channels per CTA */
#define CCH 24                    /* channel chunks per batch for einsum */
#define CH_E (CC/CCH)             /* 32 channels per CTA */

typedef unsigned long long u64;

__device__ __forceinline__ u64 pk2(float lo, float hi) {
    u64 r; asm("mov.b64 %0, {%1,%2};" : "=l"(r) : "f"(lo), "f"(hi)); return r;
}
__device__ __forceinline__ void fma2(u64 &d, u64 a, u64 b) {
    asm("fma.rn.f32x2 %0, %1, %2, %0;" : "+l"(d) : "l"(a), "l"(b));
}
__device__ __forceinline__ void unpk2(u64 v, float &lo, float &hi) {
    asm("mov.b64 {%0,%1}, %2;" : "=f"(lo), "=f"(hi) : "l"(v));
}

// ---------------------------------------------------------------------------
// Kernel 1: mask[b,s,p] = bias[s]
// ---------------------------------------------------------------------------
__global__ void init_mask_kernel(const float* __restrict__ bias,
                                 float* __restrict__ mask) {
    int i = blockIdx.x * 256 + threadIdx.x;
    if (i < MASK_SIZE) {
        int s = (i / HW) & 7;
        mask[i] = bias[s];
    }
}

// ---------------------------------------------------------------------------
// Kernel 2: conv 3x3 (C->S), per-CTA partial over 48 channels, atomicAdd out.
// Plane staged in zero-padded smem (30-wide rows), all taps branch-free.
// ---------------------------------------------------------------------------
__global__ void conv_kernel(const float* __restrict__ x,
                            const float* __restrict__ wgt,
                            float* __restrict__ mask) {
    __shared__ float plane[31 * 30];   // 930: padded, rows 0/29/30 + cols 0/29 stay zero
    __shared__ float wst[80];          // [t][s] layout, 72 used

    const int tid = threadIdx.x;
    const int b   = blockIdx.x / CGRP;
    const int g   = blockIdx.x % CGRP;
    const int c0  = g * CH_PER;

    // zero whole plane once (borders stay zero forever)
    for (int i = tid; i < 31 * 30; i += 256) plane[i] = 0.f;

    // fixed pixel assignment: p = tid + k*256 (k=0..3); p>=784 lanes compute
    // on a clamped address (harmless) and are masked at the final write.
    int p[4], baseo[4];
#pragma unroll
    for (int k = 0; k < 4; k++) {
        p[k] = tid + k * 256;
        int pv = p[k] < HW ? p[k] : (HW - 1);
        int r = pv / 28, cl = pv % 28;
        baseo[k] = r * 30 + cl;
    }

    u64 acc[8][2];
#pragma unroll
    for (int s = 0; s < 8; s++) { acc[s][0] = 0ull; acc[s][1] = 0ull; }

    const float* xb = x + (size_t)b * CC * HW;

    for (int ci = 0; ci < CH_PER; ci++) {
        const int c = c0 + ci;
        __syncthreads();  // protect plane/wst from overwrite (and cover initial zeroing)

        const float* xc = xb + (size_t)c * HW;
        for (int i = tid; i < HW; i += 256) {
            int r = i / 28, cl = i % 28;
            plane[(r + 1) * 30 + cl + 1] = xc[i];
        }
        if (tid < 72) {
            int s = tid / 9, t = tid % 9;
            wst[t * 8 + s] = wgt[((size_t)s * CC + c) * 9 + t];
        }
        __syncthreads();

#pragma unroll
        for (int t = 0; t < 9; t++) {
            const int off = (t / 3) * 30 + (t % 3);
            float n0 = plane[baseo[0] + off];
            float n1 = plane[baseo[1] + off];
            float n2 = plane[baseo[2] + off];
            float n3 = plane[baseo[3] + off];
            u64 np0 = pk2(n0, n1), np1 = pk2(n2, n3);

            float4 wa = *(const float4*)&wst[t * 8];
            float4 wb = *(const float4*)&wst[t * 8 + 4];
            u64 w0 = pk2(wa.x, wa.x), w1 = pk2(wa.y, wa.y);
            u64 w2 = pk2(wa.z, wa.z), w3 = pk2(wa.w, wa.w);
            u64 w4 = pk2(wb.x, wb.x), w5 = pk2(wb.y, wb.y);
            u64 w6 = pk2(wb.z, wb.z), w7 = pk2(wb.w, wb.w);

            fma2(acc[0][0], np0, w0); fma2(acc[0][1], np1, w0);
            fma2(acc[1][0], np0, w1); fma2(acc[1][1], np1, w1);
            fma2(acc[2][0], np0, w2); fma2(acc[2][1], np1, w2);
            fma2(acc[3][0], np0, w3); fma2(acc[3][1], np1, w3);
            fma2(acc[4][0], np0, w4); fma2(acc[4][1], np1, w4);
            fma2(acc[5][0], np0, w5); fma2(acc[5][1], np1, w5);
            fma2(acc[6][0], np0, w6); fma2(acc[6][1], np1, w6);
            fma2(acc[7][0], np0, w7); fma2(acc[7][1], np1, w7);
        }
    }

    // accumulate partials into global mask
    float* mb = mask + (size_t)b * SS * HW;
#pragma unroll
    for (int s = 0; s < 8; s++) {
        float v0, v1, v2, v3;
        unpk2(acc[s][0], v0, v1);
        unpk2(acc[s][1], v2, v3);
        float v[4] = {v0, v1, v2, v3};
#pragma unroll
        for (int k = 0; k < 4; k++)
            if (p[k] < HW) atomicAdd(&mb[s * HW + p[k]], v[k]);
    }
}

// ---------------------------------------------------------------------------
// Kernel 3: learned[b,c,s] = (1/784) * sum_p x[b,c,p] * mask[b,s,p]
// CTA = (b, 32-channel chunk). Mask staged once in smem; each warp owns 4
// channels (4x smem reuse), packed f32x2 FMAs, butterfly reduce.
// ---------------------------------------------------------------------------
__global__ void einsum_kernel(const float* __restrict__ x,
                              const float* __restrict__ mask,
                              float* __restrict__ learned) {
    __shared__ float msk[SS * HW];  // 6272 floats = 25088 B

    const int tid   = threadIdx.x;
    const int b     = blockIdx.x / CCH;
    const int chunk = blockIdx.x % CCH;

    const float* mb = mask + (size_t)b * SS * HW;
    for (int i = tid; i < (SS * HW) / 4; i += 256)
        ((float4*)msk)[i] = ((const float4*)mb)[i];
    __syncthreads();

    const int warp = tid / 32, lane = tid % 32;
    const int ch0  = chunk * CH_E + warp * 4;
    const float* xb = x + ((size_t)b * CC + ch0) * HW;

    u64 acc[2][8];
#pragma unroll
    for (int s = 0; s < 8; s++) { acc[0][s] = 0ull; acc[1][s] = 0ull; }

    for (int i = 0; i < 25; i++) {
        int pp = i * 32 + lane;
        bool v = pp < HW;
        int pc = v ? pp : 0;
        float x0 = v ? xb[pc]          : 0.f;
        float x1 = v ? xb[HW + pc]     : 0.f;
        float x2 = v ? xb[2 * HW + pc] : 0.f;
        float x3 = v ? xb[3 * HW + pc] : 0.f;
        u64 xp0 = pk2(x0, x1), xp1 = pk2(x2, x3);
#pragma unroll
        for (int s = 0; s < 8; s++) {
            float m = msk[s * HW + pc];
            u64 m2 = pk2(m, m);
            fma2(acc[0][s], xp0, m2);
            fma2(acc[1][s], xp1, m2);
        }
    }

    // unpack: out[c_local][s]
    float out[4][8];
#pragma unroll
    for (int s = 0; s < 8; s++) {
        unpk2(acc[0][s], out[0][s], out[1][s]);
        unpk2(acc[1][s], out[2][s], out[3][s]);
    }
    // full butterfly reduction over lanes for each of the 32 accumulators
#pragma unroll
    for (int c = 0; c < 4; c++)
#pragma unroll
        for (int s = 0; s < 8; s++) {
            float v = out[c][s];
#pragma unroll
            for (int o = 16; o > 0; o >>= 1)
                v += __shfl_xor_sync(0xffffffffu, v, o);
            out[c][s] = v;
        }

    if (lane == 0) {
        const float inv = 1.0f / 784.0f;
#pragma unroll
        for (int c = 0; c < 4; c++)
#pragma unroll
            for (int s = 0; s < 8; s++)
                learned[((size_t)b * CC + ch0 + c) * SS + s] = out[c][s] * inv;
    }
}

// ---------------------------------------------------------------------------
extern "C" void kernel_launch(void* const* d_in, const int* in_sizes, int n_in,
                              void* d_out, int out_size) {
    const float* x      = (const float*)d_in[0];
    const float* conv_w = (const float*)d_in[1];
    const float* conv_b = (const float*)d_in[2];

    float* out     = (float*)d_out;
    float* learned = out;                  // [B, C, S]
    float* mask    = out + LEARNED_SIZE;   // [B, S, H, W]

    init_mask_kernel<<<(MASK_SIZE + 255) / 256, 256>>>(conv_b, mask);
    conv_kernel<<<BB * CGRP, 256>>>(x, conv_w, mask);
    einsum_kernel<<<BB * CCH, 256>>>(x, mask, learned);
}

// round 2
// speedup vs baseline: 1.2256x; 1.2256x over previous
#include <cuda_runtime.h>

#define BB 64
#define CC 768
#define SS 8
#define HH 28
#define WW 28
#define HW 784
#define LEARNED_SIZE (BB*CC*SS)   /* 393216 */
#define MASK_SIZE    (BB*SS*HW)   /* 401408 */

#define CGRP 16                   /* channel groups per batch for conv */
#define CH_PER (CC/CGRP)          /* 48 channels per CTA */
#define CCH 24                    /* channel chunks per batch for einsum */
#define CH_E (CC/CCH)             /* 32 channels per CTA */

#define PSTRIDE 36                /* padded plane row stride (keeps float4 alignment, avoids bank-aligned rows) */

typedef unsigned long long u64;

__device__ __forceinline__ u64 pk2(float lo, float hi) {
    u64 r; asm("mov.b64 %0, {%1,%2};" : "=l"(r) : "f"(lo), "f"(hi)); return r;
}
__device__ __forceinline__ void fma2(u64 &d, u64 a, u64 b) {
    asm("fma.rn.f32x2 %0, %1, %2, %0;" : "+l"(d) : "l"(a), "l"(b));
}
__device__ __forceinline__ void unpk2(u64 v, float &lo, float &hi) {
    asm("mov.b64 {%0,%1}, %2;" : "=f"(lo), "=f"(hi) : "l"(v));
}

// ---------------------------------------------------------------------------
// Kernel 1: mask[b,s,p] = bias[s]  (vectorized float4; HW%4==0 so s is uniform)
// ---------------------------------------------------------------------------
__global__ void init_mask_kernel(const float* __restrict__ bias,
                                 float4* __restrict__ mask4) {
    int i = blockIdx.x * 256 + threadIdx.x;
    if (i < MASK_SIZE / 4) {
        int s = (i / (HW / 4)) & 7;
        float bv = bias[s];
        mask4[i] = make_float4(bv, bv, bv, bv);
    }
}

// ---------------------------------------------------------------------------
// Kernel 2: conv 3x3 (C->S). 196 threads/CTA, each owns 4 HORIZONTALLY
// ADJACENT pixels (row r = tid/7, cols 4q..4q+3, q = tid%7). Overlapping
// 3x3 windows: 6 smem loads + 15 packs serve all 9 taps. Weights staged as
// duplicated (w,w) u64 pairs -> tap loop is 4 broadcast LDS.128 + 16 fma2.
// Next channel's plane + weights prefetched into registers during compute.
// ---------------------------------------------------------------------------
__global__ void __launch_bounds__(196, 3)
conv_kernel(const float* __restrict__ x,
            const float* __restrict__ wgt,
            float* __restrict__ mask) {
    __shared__ float plane[30 * PSTRIDE];         // rows 0..29 padded (orig rows -1..28), cols 0..35
    __shared__ __align__(16) float wpk[144];      // [t][s] duplicated pairs: wpk[t*16 + 2s {+1}]

    const int tid = threadIdx.x;
    const int b   = blockIdx.x / CGRP;
    const int g   = blockIdx.x % CGRP;
    const int c0  = g * CH_PER;

    // zero whole plane once (padding stays zero forever)
    for (int i = tid; i < 30 * PSTRIDE; i += 196) plane[i] = 0.f;

    // pixel geometry (all 196 threads active, no masking anywhere)
    const int r = tid / 7;            // 0..27
    const int q = tid % 7;            // 0..6 -> cols 4q..4q+3
    // window covers orig rows r-1..r+1 (padded r..r+2), orig cols 4q-1..4q+4 (padded 4q..4q+5)
    const int wbase = r * PSTRIDE + 4 * q;        // float4-aligned (36r+4q ≡ 0 mod 4)

    // plane staging offsets (channel-invariant)
    int ssofs[4];
#pragma unroll
    for (int k = 0; k < 4; k++) {
        int i = tid + k * 196;
        ssofs[k] = (i / 28 + 1) * PSTRIDE + (i % 28) + 1;
    }

    // weight staging role
    const int ws = tid / 9, wt = tid % 9;         // valid when tid < 72
    const bool wrole = (tid < 72);

    const float* xb = x + ((size_t)b * CC + c0) * HW;

    // prefetch channel 0
    float pref[4];
#pragma unroll
    for (int k = 0; k < 4; k++) pref[k] = xb[tid + k * 196];
    float wpref = 0.f;
    if (wrole) wpref = wgt[((size_t)ws * CC + c0) * 9 + wt];

    u64 acc[8][2];
#pragma unroll
    for (int s = 0; s < 8; s++) { acc[s][0] = 0ull; acc[s][1] = 0ull; }

    for (int ci = 0; ci < CH_PER; ci++) {
        __syncthreads();   // previous compute done reading plane/wpk (and covers initial zeroing)

#pragma unroll
        for (int k = 0; k < 4; k++) plane[ssofs[k]] = pref[k];
        if (wrole) {
            wpk[wt * 16 + 2 * ws]     = wpref;
            wpk[wt * 16 + 2 * ws + 1] = wpref;
        }
        // prefetch next channel while this one computes
        if (ci + 1 < CH_PER) {
            const float* xc = xb + (size_t)(ci + 1) * HW;
#pragma unroll
            for (int k = 0; k < 4; k++) pref[k] = xc[tid + k * 196];
            if (wrole) wpref = wgt[((size_t)ws * CC + c0 + ci + 1) * 9 + wt];
        }
        __syncthreads();

        // load 3 rows x 6 values, build 5 shifted pairs per row
        u64 pr[3][5];
#pragma unroll
        for (int dr = 0; dr < 3; dr++) {
            const float* rp = &plane[wbase + dr * PSTRIDE];
            float4 f = *(const float4*)rp;          // v0..v3
            float2 h = *(const float2*)(rp + 4);    // v4,v5
            pr[dr][0] = pk2(f.x, f.y);
            pr[dr][1] = pk2(f.y, f.z);
            pr[dr][2] = pk2(f.z, f.w);
            pr[dr][3] = pk2(f.w, h.x);
            pr[dr][4] = pk2(h.x, h.y);
        }

#pragma unroll
        for (int t = 0; t < 9; t++) {
            const int row = t / 3, tc = t % 3;
            u64 pA = pr[row][tc];        // tap values for pixels 0,1
            u64 pB = pr[row][tc + 2];    // tap values for pixels 2,3
            const ulonglong2* wp = (const ulonglong2*)&wpk[t * 16];
            ulonglong2 w01 = wp[0], w23 = wp[1], w45 = wp[2], w67 = wp[3];
            fma2(acc[0][0], pA, w01.x); fma2(acc[0][1], pB, w01.x);
            fma2(acc[1][0], pA, w01.y); fma2(acc[1][1], pB, w01.y);
            fma2(acc[2][0], pA, w23.x); fma2(acc[2][1], pB, w23.x);
            fma2(acc[3][0], pA, w23.y); fma2(acc[3][1], pB, w23.y);
            fma2(acc[4][0], pA, w45.x); fma2(acc[4][1], pB, w45.x);
            fma2(acc[5][0], pA, w45.y); fma2(acc[5][1], pB, w45.y);
            fma2(acc[6][0], pA, w67.x); fma2(acc[6][1], pB, w67.x);
            fma2(acc[7][0], pA, w67.y); fma2(acc[7][1], pB, w67.y);
        }
    }

    // accumulate partials into global mask (spread-address REDG, cheap)
    float* mb = mask + (size_t)b * SS * HW;
    const int p0 = r * 28 + 4 * q;
#pragma unroll
    for (int s = 0; s < 8; s++) {
        float v0, v1, v2, v3;
        unpk2(acc[s][0], v0, v1);
        unpk2(acc[s][1], v2, v3);
        float* mp = &mb[s * HW + p0];
        atomicAdd(mp + 0, v0);
        atomicAdd(mp + 1, v1);
        atomicAdd(mp + 2, v2);
        atomicAdd(mp + 3, v3);
    }
}

// ---------------------------------------------------------------------------
// Kernel 3: learned[b,c,s] = (1/784) * sum_p x[b,c,p] * mask[b,s,p]
// CTA = (b, 32-channel chunk). Mask staged once in smem; each warp owns 4
// channels (4x smem reuse), packed f32x2 FMAs, butterfly reduce.
// ---------------------------------------------------------------------------
__global__ void einsum_kernel(const float* __restrict__ x,
                              const float* __restrict__ mask,
                              float* __restrict__ learned) {
    __shared__ float msk[SS * HW];  // 6272 floats = 25088 B

    const int tid   = threadIdx.x;
    const int b     = blockIdx.x / CCH;
    const int chunk = blockIdx.x % CCH;

    const float* mb = mask + (size_t)b * SS * HW;
    for (int i = tid; i < (SS * HW) / 4; i += 256)
        ((float4*)msk)[i] = ((const float4*)mb)[i];
    __syncthreads();

    const int warp = tid / 32, lane = tid % 32;
    const int ch0  = chunk * CH_E + warp * 4;
    const float* xb = x + ((size_t)b * CC + ch0) * HW;

    u64 acc[2][8];
#pragma unroll
    for (int s = 0; s < 8; s++) { acc[0][s] = 0ull; acc[1][s] = 0ull; }

    for (int i = 0; i < 25; i++) {
        int pp = i * 32 + lane;
        bool v = pp < HW;
        int pc = v ? pp : 0;
        float x0 = v ? xb[pc]          : 0.f;
        float x1 = v ? xb[HW + pc]     : 0.f;
        float x2 = v ? xb[2 * HW + pc] : 0.f;
        float x3 = v ? xb[3 * HW + pc] : 0.f;
        u64 xp0 = pk2(x0, x1), xp1 = pk2(x2, x3);
#pragma unroll
        for (int s = 0; s < 8; s++) {
            float m = msk[s * HW + pc];
            u64 m2 = pk2(m, m);
            fma2(acc[0][s], xp0, m2);
            fma2(acc[1][s], xp1, m2);
        }
    }

    float out[4][8];
#pragma unroll
    for (int s = 0; s < 8; s++) {
        unpk2(acc[0][s], out[0][s], out[1][s]);
        unpk2(acc[1][s], out[2][s], out[3][s]);
    }
#pragma unroll
    for (int c = 0; c < 4; c++)
#pragma unroll
        for (int s = 0; s < 8; s++) {
            float v = out[c][s];
#pragma unroll
            for (int o = 16; o > 0; o >>= 1)
                v += __shfl_xor_sync(0xffffffffu, v, o);
            out[c][s] = v;
        }

    if (lane == 0) {
        const float inv = 1.0f / 784.0f;
#pragma unroll
        for (int c = 0; c < 4; c++)
#pragma unroll
            for (int s = 0; s < 8; s++)
                learned[((size_t)b * CC + ch0 + c) * SS + s] = out[c][s] * inv;
    }
}

// ---------------------------------------------------------------------------
extern "C" void kernel_launch(void* const* d_in, const int* in_sizes, int n_in,
                              void* d_out, int out_size) {
    const float* x      = (const float*)d_in[0];
    const float* conv_w = (const float*)d_in[1];
    const float* conv_b = (const float*)d_in[2];

    float* out     = (float*)d_out;
    float* learned = out;                  // [B, C, S]
    float* mask    = out + LEARNED_SIZE;   // [B, S, H, W]

    init_mask_kernel<<<(MASK_SIZE / 4 + 255) / 256, 256>>>(conv_b, (float4*)mask);
    conv_kernel<<<BB * CGRP, 196>>>(x, conv_w, mask);
    einsum_kernel<<<BB * CCH, 256>>>(x, mask, learned);
}